// round 10
// baseline (speedup 1.0000x reference)
#include <cuda_runtime.h>
#include <cuda_fp16.h>
#include <cstdint>

// ---------------- problem constants ----------------
#define MM   8192
#define NN   2048
#define KIN  2048
#define KK   4096
#define NELEM_GRID ((double)KIN*NN*8)

// ---------------- GEMM tiling ----------------
// CTA = 128 threads (2x2 warps), warp tile 64x64, swizzled smem, 3 CTAs/SM.
#define BM 128
#define BN 128
#define KTILE 64              // K halves per stage (128 B per row)
#define NSTAGE 2
#define NT (KK / KTILE)       // 64

#define STB (BM * 128)                       // 16384 bytes per operand stage
#define AOFF(s) ((s) * STB)
#define BOFF(s) (NSTAGE * STB + (s) * STB)
#define SMEM_TOTAL (2 * NSTAGE * STB)        // 65536 -> 3 CTAs/SM

// ---------------- device scratch ----------------
__device__ __half g_A[(size_t)MM * KK];    // [M][K]: [x | basis]
__device__ __half g_B[(size_t)NN * KK];    // [N][K]: [Wb | W2^T]
__device__ unsigned long long g_meanacc;   // fixed-point (2^-32) grid sum

// ---------------- helpers ----------------
__device__ __forceinline__ void cp16(uint32_t smem, const void* gmem) {
    asm volatile("cp.async.cg.shared.global [%0], [%1], 16;" :: "r"(smem), "l"(gmem));
}

__device__ __forceinline__ void ldsm4(uint32_t* r, uint32_t addr) {
    asm volatile("ldmatrix.sync.aligned.m8n8.x4.shared.b16 {%0,%1,%2,%3}, [%4];"
                 : "=r"(r[0]), "=r"(r[1]), "=r"(r[2]), "=r"(r[3]) : "r"(addr));
}

__device__ __forceinline__ void mma_f16(float* d, const uint32_t* a, const uint32_t* b) {
    asm volatile(
        "mma.sync.aligned.m16n8k16.row.col.f32.f16.f16.f32 "
        "{%0,%1,%2,%3}, {%4,%5,%6,%7}, {%8,%9}, {%0,%1,%2,%3};"
        : "+f"(d[0]), "+f"(d[1]), "+f"(d[2]), "+f"(d[3])
        : "r"(a[0]), "r"(a[1]), "r"(a[2]), "r"(a[3]), "r"(b[0]), "r"(b[1]));
}

// ======================= prep 1: grid reduce + transpose + mean ===========
__global__ void k_gridsum(const float* __restrict__ grid) {
    __shared__ float tile[32][33];
    __shared__ float red[256];
    int i0 = blockIdx.x * 32, o0 = blockIdx.y * 32;
    int tx = threadIdx.x & 31, ty = threadIdx.x >> 5;   // 32 x 8
    const float4* g4 = reinterpret_cast<const float4*>(grid);
    float loc = 0.f;
    #pragma unroll
    for (int r = ty; r < 32; r += 8) {
        size_t idx8 = (size_t)(i0 + r) * NN + (o0 + tx);
        float4 p = g4[idx8 * 2];
        float4 q = g4[idx8 * 2 + 1];
        float s = ((p.x + p.y) + (p.z + p.w)) + ((q.x + q.y) + (q.z + q.w));
        tile[r][tx] = s;
        loc += s;
    }
    red[threadIdx.x] = loc;
    __syncthreads();
    #pragma unroll
    for (int r = ty; r < 32; r += 8)
        g_B[(size_t)(o0 + r) * KK + KIN + i0 + tx] = __float2half_rn(tile[tx][r]);
    for (int off = 128; off > 0; off >>= 1) {
        if (threadIdx.x < off) red[threadIdx.x] += red[threadIdx.x + off];
        __syncthreads();
    }
    if (threadIdx.x == 0) {
        long long q = llrint((double)red[0] * 4294967296.0);
        atomicAdd(&g_meanacc, (unsigned long long)q);
    }
}

// ======================= prep 2: Wb -> half B[N][0:2048] ==================
__global__ void k_roundWb(const float* __restrict__ bw) {
    int t = blockIdx.x * 256 + threadIdx.x;      // one float4
    int n = t >> 9, k4 = t & 511;
    const float4* s4 = reinterpret_cast<const float4*>(bw);
    float4 v = s4[(size_t)t];
    __half2* dst = reinterpret_cast<__half2*>(g_B) + (size_t)n * (KK / 2) + k4 * 2;
    dst[0] = __floats2half2_rn(v.x, v.y);
    dst[1] = __floats2half2_rn(v.z, v.w);
}

// ======================= prep 3: build A = [x | basis] (half) =============
__global__ void k_buildA(const float* __restrict__ x) {
    int t = blockIdx.x * 256 + threadIdx.x;
    int b = t >> 9, c4 = t & 511;
    const float4* x4 = reinterpret_cast<const float4*>(x);
    float4 v = x4[(size_t)b * 512 + c4];
    double acc = (double)(long long)g_meanacc;
    float m = (float)(acc * (1.0 / 4294967296.0) / NELEM_GRID);
    __half2* A2 = reinterpret_cast<__half2*>(g_A);
    size_t base = (size_t)b * (KK / 2) + c4 * 2;
    A2[base + 0] = __floats2half2_rn(v.x, v.y);
    A2[base + 1] = __floats2half2_rn(v.z, v.w);
    float dx = v.x - m, dy = v.y - m, dz = v.z - m, dw = v.w - m;
    size_t base2 = base + (KIN / 2);
    A2[base2 + 0] = __floats2half2_rn(__expf(-dx * dx), __expf(-dy * dy));
    A2[base2 + 1] = __floats2half2_rn(__expf(-dz * dz), __expf(-dw * dw));
}

// ====== main GEMM: 128x128x64, 128 thr, warp 64x64, swizzled, 3 CTA/SM ====
__global__ __launch_bounds__(128, 3) void k_gemm(float* __restrict__ out) {
    extern __shared__ char smc[];
    uint32_t sb = (uint32_t)__cvta_generic_to_shared(smc);

    // reset mean accumulator for the next graph replay
    if (blockIdx.x == 0 && blockIdx.y == 0 && threadIdx.x == 0) g_meanacc = 0ULL;

    int tid  = threadIdx.x;
    int warp = tid >> 5, lane = tid & 31;
    int wm = warp & 1;         // 2 warps along M -> 64 rows each
    int wn = warp >> 1;        // 2 warps along N -> 64 cols each
    int g  = lane >> 2;        // 0..7
    int tg = lane & 3;         // 0..3
    int m0 = blockIdx.y * BM;
    int n0 = blockIdx.x * BN;

    // ---- swizzled ldmatrix lane addressing ----
    // A: row = wm*64 + mf*16 + (lane&15); chunk(s) = (2s | (lane>>4)) ^ (lane&7)
    // B: row = wn*64 + nf2*16 + (li>>1)*8 + lr; chunk(s) = (2s | (li&1)) ^ lr
    int e   = lane & 7;
    int ab0 = lane >> 4;
    int li  = lane >> 3;
    uint32_t a_row = (uint32_t)((wm * 64 + (lane & 15)) * 128);
    uint32_t b_row = (uint32_t)((wn * 64 + ((li >> 1) * 8) + e) * 128);
    int bb0 = li & 1;

    // ---- cp.async: one row per thread, 8 swizzled 16B chunks per operand --
    const __half* Ag = g_A + (size_t)(m0 + tid) * KK;
    const __half* Bg = g_B + (size_t)(n0 + tid) * KK;
    uint32_t stA = (uint32_t)(tid * 128);
    int rx = tid & 7;          // row swizzle key

    float acc[4][8][4];        // 64x64 warp tile
    #pragma unroll
    for (int i = 0; i < 4; i++)
        #pragma unroll
        for (int j = 0; j < 8; j++)
            #pragma unroll
            for (int k = 0; k < 4; k++) acc[i][j][k] = 0.f;

    // prologue: stage 0
    #pragma unroll
    for (int i = 0; i < 8; ++i) {
        uint32_t sw = (uint32_t)((i ^ rx) << 4);
        cp16(sb + AOFF(0) + stA + sw, Ag + i * 8);
        cp16(sb + BOFF(0) + stA + sw, Bg + i * 8);
    }
    asm volatile("cp.async.commit_group;");

    #pragma unroll 1
    for (int kt = 0; kt < NT; ++kt) {
        if (kt + 1 < NT) {
            int k0 = (kt + 1) * KTILE;
            int s  = (kt + 1) & 1;
            #pragma unroll
            for (int i = 0; i < 8; ++i) {
                uint32_t sw = (uint32_t)((i ^ rx) << 4);
                cp16(sb + AOFF(s) + stA + sw, Ag + k0 + i * 8);
                cp16(sb + BOFF(s) + stA + sw, Bg + k0 + i * 8);
            }
            asm volatile("cp.async.commit_group;");
            asm volatile("cp.async.wait_group 1;");
        } else {
            asm volatile("cp.async.wait_group 0;");
        }
        __syncthreads();

        int buf = kt & 1;
        uint32_t abase = sb + AOFF(buf) + a_row;
        uint32_t bbase = sb + BOFF(buf) + b_row;

        #pragma unroll
        for (int s = 0; s < 4; ++s) {                // four k16 slices
            uint32_t ac0 = (uint32_t)((((2 * s) | ab0) ^ e) << 4);
            uint32_t bc0 = (uint32_t)((((2 * s) | bb0) ^ e) << 4);
            uint32_t af[4][4];
            #pragma unroll
            for (int mf = 0; mf < 4; ++mf)
                ldsm4(af[mf], abase + mf * (16 * 128) + ac0);
            #pragma unroll
            for (int nf2 = 0; nf2 < 4; ++nf2) {      // 4 x (two n8 tiles)
                uint32_t bt[4];
                ldsm4(bt, bbase + nf2 * (16 * 128) + bc0);
                uint32_t b0[2] = {bt[0], bt[1]};
                uint32_t b1[2] = {bt[2], bt[3]};
                #pragma unroll
                for (int mf = 0; mf < 4; ++mf) {
                    mma_f16(acc[mf][nf2 * 2 + 0], af[mf], b0);
                    mma_f16(acc[mf][nf2 * 2 + 1], af[mf], b1);
                }
            }
        }
        __syncthreads();
    }

    // epilogue
    #pragma unroll
    for (int mf = 0; mf < 4; ++mf) {
        #pragma unroll
        for (int nf = 0; nf < 8; ++nf) {
            int row0 = m0 + wm * 64 + mf * 16 + g;
            int col  = n0 + wn * 64 + nf * 8 + tg * 2;
            float2 v0 = make_float2(acc[mf][nf][0], acc[mf][nf][1]);
            float2 v1 = make_float2(acc[mf][nf][2], acc[mf][nf][3]);
            *reinterpret_cast<float2*>(&out[(size_t)row0 * NN + col])       = v0;
            *reinterpret_cast<float2*>(&out[(size_t)(row0 + 8) * NN + col]) = v1;
        }
    }
}

// ============================= launch =====================================
extern "C" void kernel_launch(void* const* d_in, const int* in_sizes, int n_in,
                              void* d_out, int out_size) {
    const float* x    = (const float*)d_in[0];   // (8192, 2048)
    const float* bw   = (const float*)d_in[1];   // (2048, 2048)
    const float* grid = (const float*)d_in[2];   // (2048, 2048, 8)
    float* out = (float*)d_out;                  // (8192, 2048)

    cudaFuncSetAttribute(k_gemm, cudaFuncAttributeMaxDynamicSharedMemorySize, SMEM_TOTAL);

    k_gridsum<<<dim3(KIN / 32, NN / 32), 256>>>(grid);
    k_roundWb<<<(NN * KIN / 4) / 256, 256>>>(bw);
    k_buildA<<<(MM * KIN / 4) / 256, 256>>>(x);
    k_gemm<<<dim3(NN / BN, MM / BM), 128, SMEM_TOTAL>>>(out);
}

// round 11
// speedup vs baseline: 1.2529x; 1.2529x over previous
#include <cuda_runtime.h>
#include <cuda_fp16.h>
#include <cstdint>

// ---------------- problem constants ----------------
#define MM   8192
#define NN   2048
#define KIN  2048
#define KK   4096
#define NELEM_GRID ((double)KIN*NN*8)

// ---------------- GEMM tiling (fp16 operands, fp32 accum) -----------------
#define BM 128
#define BN 128
#define KTILE 32              // K halves per stage
#define ASTR 40               // padded row stride in halves (80 B) - conflict-free
#define NSTAGE 4
#define NT (KK / KTILE)       // 128

#define ABYTES (BM * ASTR * 2)               // 10240
#define BBYTES (BN * ASTR * 2)               // 10240
#define AOFF(s) ((s) * ABYTES)
#define BOFF(s) (NSTAGE * ABYTES + (s) * BBYTES)
#define SMEM_TOTAL (NSTAGE * (ABYTES + BBYTES))   // 81920  -> 2 CTAs/SM

// ---------------- device scratch ----------------
__device__ __half g_A[(size_t)MM * KK];    // [M][K]: [x | basis]
__device__ __half g_B[(size_t)NN * KK];    // [N][K]: [Wb | W2^T]
__device__ unsigned long long g_meanacc;   // fixed-point (2^-32) grid sum

// ---------------- helpers ----------------
__device__ __forceinline__ void cp16(uint32_t smem, const void* gmem) {
    asm volatile("cp.async.cg.shared.global [%0], [%1], 16;" :: "r"(smem), "l"(gmem));
}

__device__ __forceinline__ void ldsm4(uint32_t* r, uint32_t addr) {
    asm volatile("ldmatrix.sync.aligned.m8n8.x4.shared.b16 {%0,%1,%2,%3}, [%4];"
                 : "=r"(r[0]), "=r"(r[1]), "=r"(r[2]), "=r"(r[3]) : "r"(addr));
}

__device__ __forceinline__ void mma_f16(float* d, const uint32_t* a, const uint32_t* b) {
    asm volatile(
        "mma.sync.aligned.m16n8k16.row.col.f32.f16.f16.f32 "
        "{%0,%1,%2,%3}, {%4,%5,%6,%7}, {%8,%9}, {%0,%1,%2,%3};"
        : "+f"(d[0]), "+f"(d[1]), "+f"(d[2]), "+f"(d[3])
        : "r"(a[0]), "r"(a[1]), "r"(a[2]), "r"(a[3]), "r"(b[0]), "r"(b[1]));
}

__device__ __forceinline__ float4 ldcs4(const float4* p) {
    return __ldcs(p);
}

// ======================= prep 1: grid reduce + transpose + mean ===========
// g_B[o][2048+i] = half( sum_g grid[i][o][g] ); deterministic fixed-point mean acc.
__global__ void k_gridsum(const float* __restrict__ grid) {
    __shared__ float tile[32][33];
    __shared__ float red[256];
    int i0 = blockIdx.x * 32, o0 = blockIdx.y * 32;
    int tx = threadIdx.x & 31, ty = threadIdx.x >> 5;   // 32 x 8
    const float4* g4 = reinterpret_cast<const float4*>(grid);
    float loc = 0.f;
    #pragma unroll
    for (int r = ty; r < 32; r += 8) {
        size_t idx8 = (size_t)(i0 + r) * NN + (o0 + tx);
        float4 p = ldcs4(g4 + idx8 * 2);
        float4 q = ldcs4(g4 + idx8 * 2 + 1);
        float s = ((p.x + p.y) + (p.z + p.w)) + ((q.x + q.y) + (q.z + q.w));
        tile[r][tx] = s;
        loc += s;
    }
    red[threadIdx.x] = loc;
    __syncthreads();
    #pragma unroll
    for (int r = ty; r < 32; r += 8)
        g_B[(size_t)(o0 + r) * KK + KIN + i0 + tx] = __float2half_rn(tile[tx][r]);
    for (int off = 128; off > 0; off >>= 1) {
        if (threadIdx.x < off) red[threadIdx.x] += red[threadIdx.x + off];
        __syncthreads();
    }
    if (threadIdx.x == 0) {
        long long q = llrint((double)red[0] * 4294967296.0);
        atomicAdd(&g_meanacc, (unsigned long long)q);
    }
}

// ======================= prep 2: Wb -> half B[N][0:2048] ==================
// 2 float4 per thread, streaming loads.
__global__ void k_roundWb(const float* __restrict__ bw) {
    int t = blockIdx.x * 256 + threadIdx.x;      // two float4 per thread
    const float4* s4 = reinterpret_cast<const float4*>(bw);
    float4 v0 = ldcs4(s4 + (size_t)t * 2);
    float4 v1 = ldcs4(s4 + (size_t)t * 2 + 1);
    __half2* dst = reinterpret_cast<__half2*>(g_B);
    int n  = t >> 8;             // 256 float4-pairs per row (KK rows? no: per N row 512 f4)
    int c8 = t & 255;            // pair index within row (512 f4 / 2)
    size_t base = (size_t)n * (KK / 2) + c8 * 4;
    dst[base + 0] = __floats2half2_rn(v0.x, v0.y);
    dst[base + 1] = __floats2half2_rn(v0.z, v0.w);
    dst[base + 2] = __floats2half2_rn(v1.x, v1.y);
    dst[base + 3] = __floats2half2_rn(v1.z, v1.w);
}

// ======================= prep 3: build A = [x | basis] (half) =============
// 4 float4 per thread (MLP 4), streaming loads of x.
__global__ void k_buildA(const float* __restrict__ x) {
    int t = blockIdx.x * 256 + threadIdx.x;
    int b  = t >> 7;                 // row (128 threads per row)
    int c4 = (t & 127) * 4;          // first float4 index in row (512 per row)
    const float4* x4 = reinterpret_cast<const float4*>(x) + (size_t)b * 512 + c4;
    float4 v0 = ldcs4(x4 + 0);
    float4 v1 = ldcs4(x4 + 1);
    float4 v2 = ldcs4(x4 + 2);
    float4 v3 = ldcs4(x4 + 3);
    double accd = (double)(long long)g_meanacc;
    float m = (float)(accd * (1.0 / 4294967296.0) / NELEM_GRID);
    __half2* A2 = reinterpret_cast<__half2*>(g_A);
    size_t base = (size_t)b * (KK / 2) + c4 * 2;
    A2[base + 0] = __floats2half2_rn(v0.x, v0.y);
    A2[base + 1] = __floats2half2_rn(v0.z, v0.w);
    A2[base + 2] = __floats2half2_rn(v1.x, v1.y);
    A2[base + 3] = __floats2half2_rn(v1.z, v1.w);
    A2[base + 4] = __floats2half2_rn(v2.x, v2.y);
    A2[base + 5] = __floats2half2_rn(v2.z, v2.w);
    A2[base + 6] = __floats2half2_rn(v3.x, v3.y);
    A2[base + 7] = __floats2half2_rn(v3.z, v3.w);
    size_t base2 = base + (KIN / 2);
    float d0x = v0.x - m, d0y = v0.y - m, d0z = v0.z - m, d0w = v0.w - m;
    float d1x = v1.x - m, d1y = v1.y - m, d1z = v1.z - m, d1w = v1.w - m;
    float d2x = v2.x - m, d2y = v2.y - m, d2z = v2.z - m, d2w = v2.w - m;
    float d3x = v3.x - m, d3y = v3.y - m, d3z = v3.z - m, d3w = v3.w - m;
    A2[base2 + 0] = __floats2half2_rn(__expf(-d0x * d0x), __expf(-d0y * d0y));
    A2[base2 + 1] = __floats2half2_rn(__expf(-d0z * d0z), __expf(-d0w * d0w));
    A2[base2 + 2] = __floats2half2_rn(__expf(-d1x * d1x), __expf(-d1y * d1y));
    A2[base2 + 3] = __floats2half2_rn(__expf(-d1z * d1z), __expf(-d1w * d1w));
    A2[base2 + 4] = __floats2half2_rn(__expf(-d2x * d2x), __expf(-d2y * d2y));
    A2[base2 + 5] = __floats2half2_rn(__expf(-d2z * d2z), __expf(-d2w * d2w));
    A2[base2 + 6] = __floats2half2_rn(__expf(-d3x * d3x), __expf(-d3y * d3y));
    A2[base2 + 7] = __floats2half2_rn(__expf(-d3z * d3z), __expf(-d3w * d3w));
}

// ======================= main GEMM: 128x128x32, fp16 mma.sync (R5) ========
__global__ __launch_bounds__(256, 2) void k_gemm(float* __restrict__ out) {
    extern __shared__ char smc[];
    uint32_t sb = (uint32_t)__cvta_generic_to_shared(smc);

    // reset mean accumulator for the next graph replay
    if (blockIdx.x == 0 && blockIdx.y == 0 && threadIdx.x == 0) g_meanacc = 0ULL;

    int tid  = threadIdx.x;
    int warp = tid >> 5, lane = tid & 31;
    int wm = warp & 3;         // 4 warps along M -> 32 rows each
    int wn = warp >> 2;        // 2 warps along N -> 64 cols each
    int g  = lane >> 2;        // 0..7
    int tg = lane & 3;         // 0..3
    int m0 = blockIdx.y * BM;
    int n0 = blockIdx.x * BN;

    // ldmatrix per-lane offsets (bytes, within one stage)
    int li = lane >> 3, lr = lane & 7;
    uint32_t a_lane = (uint32_t)((lane & 15) * (ASTR * 2) + (lane >> 4) * 16);
    uint32_t a_warp = (uint32_t)(wm * 32 * (ASTR * 2));
    uint32_t b_lane = (uint32_t)((((li >> 1) * 8) + lr) * (ASTR * 2) + (li & 1) * 16);
    uint32_t b_warp = (uint32_t)(wn * 64 * (ASTR * 2));

    // cp.async mapping: per operand 512 16B-chunks, 2/thread
    int r0 = tid >> 1;                 // row 0..127
    int c0 = (tid & 1) * 2;            // chunk 0/2 (+1)
    const __half* Ag = g_A + (size_t)(m0 + r0) * KK + c0 * 8;
    const __half* Bg = g_B + (size_t)(n0 + r0) * KK + c0 * 8;
    uint32_t dA = (uint32_t)(r0 * (ASTR * 2) + c0 * 16);

    float acc[2][8][4];
    #pragma unroll
    for (int i = 0; i < 2; i++)
        #pragma unroll
        for (int j = 0; j < 8; j++)
            #pragma unroll
            for (int k = 0; k < 4; k++) acc[i][j][k] = 0.f;

    // prologue: stages 0..2
    #pragma unroll
    for (int s = 0; s < NSTAGE - 1; ++s) {
        int k0 = s * KTILE;
        cp16(sb + AOFF(s) + dA,      Ag + k0);
        cp16(sb + AOFF(s) + dA + 16, Ag + k0 + 8);
        cp16(sb + BOFF(s) + dA,      Bg + k0);
        cp16(sb + BOFF(s) + dA + 16, Bg + k0 + 8);
        asm volatile("cp.async.commit_group;");
    }

    #pragma unroll 1
    for (int kt = 0; kt < NT; ++kt) {
        asm volatile("cp.async.wait_group %0;" :: "n"(NSTAGE - 2));
        __syncthreads();

        if (kt + NSTAGE - 1 < NT) {
            int s  = (kt + NSTAGE - 1) & (NSTAGE - 1);
            int k0 = (kt + NSTAGE - 1) * KTILE;
            cp16(sb + AOFF(s) + dA,      Ag + k0);
            cp16(sb + AOFF(s) + dA + 16, Ag + k0 + 8);
            cp16(sb + BOFF(s) + dA,      Bg + k0);
            cp16(sb + BOFF(s) + dA + 16, Bg + k0 + 8);
        }
        asm volatile("cp.async.commit_group;");

        int buf = kt & (NSTAGE - 1);
        uint32_t abase = sb + AOFF(buf) + a_warp + a_lane;
        uint32_t bbase = sb + BOFF(buf) + b_warp + b_lane;

        #pragma unroll
        for (int s = 0; s < 2; ++s) {                 // two k16 slices
            uint32_t af[2][4];
            ldsm4(af[0], abase + s * 32);
            ldsm4(af[1], abase + s * 32 + 16 * (ASTR * 2));
            #pragma unroll
            for (int nf2 = 0; nf2 < 4; ++nf2) {       // 4 x (two n8 tiles)
                uint32_t bt[4];
                ldsm4(bt, bbase + s * 32 + nf2 * (16 * (ASTR * 2)));
                uint32_t b0[2] = {bt[0], bt[1]};
                uint32_t b1[2] = {bt[2], bt[3]};
                #pragma unroll
                for (int mf = 0; mf < 2; ++mf) {
                    mma_f16(acc[mf][nf2 * 2 + 0], af[mf], b0);
                    mma_f16(acc[mf][nf2 * 2 + 1], af[mf], b1);
                }
            }
        }
        __syncthreads();
    }

    // epilogue
    #pragma unroll
    for (int mf = 0; mf < 2; ++mf) {
        #pragma unroll
        for (int nf = 0; nf < 8; ++nf) {
            int row0 = m0 + wm * 32 + mf * 16 + g;
            int col  = n0 + wn * 64 + nf * 8 + tg * 2;
            float2 v0 = make_float2(acc[mf][nf][0], acc[mf][nf][1]);
            float2 v1 = make_float2(acc[mf][nf][2], acc[mf][nf][3]);
            *reinterpret_cast<float2*>(&out[(size_t)row0 * NN + col])       = v0;
            *reinterpret_cast<float2*>(&out[(size_t)(row0 + 8) * NN + col]) = v1;
        }
    }
}

// ============================= launch =====================================
extern "C" void kernel_launch(void* const* d_in, const int* in_sizes, int n_in,
                              void* d_out, int out_size) {
    const float* x    = (const float*)d_in[0];   // (8192, 2048)
    const float* bw   = (const float*)d_in[1];   // (2048, 2048)
    const float* grid = (const float*)d_in[2];   // (2048, 2048, 8)
    float* out = (float*)d_out;                  // (8192, 2048)

    cudaFuncSetAttribute(k_gemm, cudaFuncAttributeMaxDynamicSharedMemorySize, SMEM_TOTAL);

    k_gridsum<<<dim3(KIN / 32, NN / 32), 256>>>(grid);
    k_roundWb<<<(NN * KIN / 8) / 256, 256>>>(bw);
    k_buildA<<<(MM * KIN / 16) / 256, 256>>>(x);
    k_gemm<<<dim3(NN / BN, MM / BM), 256, SMEM_TOTAL>>>(out);
}

// round 12
// speedup vs baseline: 1.6636x; 1.3278x over previous
#include <cuda_runtime.h>
#include <cuda_fp16.h>
#include <cstdint>

// ---------------- problem constants ----------------
#define MM   8192
#define NN   2048
#define KIN  2048
#define KK   4096
#define NELEM_GRID ((double)KIN*NN*8)

// ---------------- GEMM tiling (fp16 operands, fp32 accum) -----------------
// A via cp.async smem (R5 path). B via direct fragment LDG from L2.
#define BM 128
#define BN 128
#define KTILE 32              // K halves per A stage
#define ASTR 40               // padded row stride in halves (80 B) - conflict-free
#define NSTAGE 4
#define NT (KK / KTILE)       // 128

#define ABYTES (BM * ASTR * 2)               // 10240
#define AOFF(s) ((s) * ABYTES)
#define SMEM_TOTAL (NSTAGE * ABYTES)         // 40960

// B fragment-major layout: slot(S, J, l) = uint2 (8 bytes)
//   S = k16-slice (0..255), J = n8-tile (0..255), l = lane (0..31)
//   lane l holds: n = J*8 + l/4, k = S*16 + (l%4)*2 + {0,1} (reg x) and +8 (reg y)
#define NSLICE 256
#define NJ     256
// one extra slice of padding so the tail prefetch never faults
__device__ uint2 g_Bf[(size_t)(NSLICE + 1) * NJ * 32];
__device__ __half g_A[(size_t)MM * KK];    // [M][K]: [x | basis]
__device__ unsigned long long g_meanacc;   // fixed-point (2^-32) grid sum

// ---------------- helpers ----------------
__device__ __forceinline__ void cp16(uint32_t smem, const void* gmem) {
    asm volatile("cp.async.cg.shared.global [%0], [%1], 16;" :: "r"(smem), "l"(gmem));
}

__device__ __forceinline__ void ldsm4(uint32_t* r, uint32_t addr) {
    asm volatile("ldmatrix.sync.aligned.m8n8.x4.shared.b16 {%0,%1,%2,%3}, [%4];"
                 : "=r"(r[0]), "=r"(r[1]), "=r"(r[2]), "=r"(r[3]) : "r"(addr));
}

__device__ __forceinline__ void mma_f16(float* d, const uint32_t* a, uint32_t b0, uint32_t b1) {
    asm volatile(
        "mma.sync.aligned.m16n8k16.row.col.f32.f16.f16.f32 "
        "{%0,%1,%2,%3}, {%4,%5,%6,%7}, {%8,%9}, {%0,%1,%2,%3};"
        : "+f"(d[0]), "+f"(d[1]), "+f"(d[2]), "+f"(d[3])
        : "r"(a[0]), "r"(a[1]), "r"(a[2]), "r"(a[3]), "r"(b0), "r"(b1));
}

__device__ __forceinline__ uint32_t pack_h2(float lo, float hi) {
    __half2 h = __floats2half2_rn(lo, hi);
    return *reinterpret_cast<uint32_t*>(&h);
}

// ======================= prep 1: grid reduce -> W2 fragments + mean =======
// W2[i][o] = sum_g grid[i][o][g], written straight into g_Bf fragment slots
// (S = 128 + i/16, J = o/8). Deterministic fixed-point mean accumulation.
__global__ void k_gridsum(const float* __restrict__ grid) {
    __shared__ float tile[32][33];
    __shared__ float red[256];
    int i0 = blockIdx.x * 32, o0 = blockIdx.y * 32;
    int tx = threadIdx.x & 31, ty = threadIdx.x >> 5;   // 32 x 8
    const float4* g4 = reinterpret_cast<const float4*>(grid);
    float loc = 0.f;
    #pragma unroll
    for (int r = ty; r < 32; r += 8) {
        size_t idx8 = (size_t)(i0 + r) * NN + (o0 + tx);
        float4 p = g4[idx8 * 2];
        float4 q = g4[idx8 * 2 + 1];
        float s = ((p.x + p.y) + (p.z + p.w)) + ((q.x + q.y) + (q.z + q.w));
        tile[r][tx] = s;   // tile[i_local][o_local]
        loc += s;
    }
    red[threadIdx.x] = loc;
    __syncthreads();

    // write phase: 256 threads cover 2 S x 4 J x 32 lanes = 256 slots
    {
        int t  = threadIdx.x;
        int sS = t >> 7;            // 0..1
        int sJ = (t >> 5) & 3;      // 0..3
        int l  = t & 31;            // lane
        int o_loc = sJ * 8 + (l >> 2);
        int i_loc = sS * 16 + (l & 3) * 2;
        uint2 u;
        u.x = pack_h2(tile[i_loc][o_loc],     tile[i_loc + 1][o_loc]);
        u.y = pack_h2(tile[i_loc + 8][o_loc], tile[i_loc + 9][o_loc]);
        int S = 128 + (i0 >> 4) + sS;
        int J = (o0 >> 3) + sJ;
        g_Bf[((size_t)S * NJ + J) * 32 + l] = u;
    }

    for (int off = 128; off > 0; off >>= 1) {
        if (threadIdx.x < off) red[threadIdx.x] += red[threadIdx.x + off];
        __syncthreads();
    }
    if (threadIdx.x == 0) {
        long long q = llrint((double)red[0] * 4294967296.0);
        atomicAdd(&g_meanacc, (unsigned long long)q);
    }
}

// ======================= prep 2: Wb -> fragment slots (S in [0,128)) ======
__global__ void k_packWb(const float* __restrict__ bw) {
    int t = blockIdx.x * 256 + threadIdx.x;  // one slot per thread, 1M total
    int S = t >> 13;            // 0..127  (8192 slots per S)
    int J = (t >> 5) & 255;     // 0..255
    int l = t & 31;             // lane
    int n  = J * 8 + (l >> 2);
    int k0 = S * 16 + (l & 3) * 2;
    const float2* bw2 = reinterpret_cast<const float2*>(bw);
    float2 a = bw2[(size_t)n * (KIN / 2) + (k0 >> 1)];
    float2 b = bw2[(size_t)n * (KIN / 2) + (k0 >> 1) + 4];
    uint2 u;
    u.x = pack_h2(a.x, a.y);
    u.y = pack_h2(b.x, b.y);
    g_Bf[((size_t)S * NJ + J) * 32 + l] = u;
}

// ======================= prep 3: build A = [x | basis] (half) =============
__global__ void k_buildA(const float* __restrict__ x) {
    int t = blockIdx.x * 256 + threadIdx.x;
    int b = t >> 9, c4 = t & 511;
    const float4* x4 = reinterpret_cast<const float4*>(x);
    float4 v = x4[(size_t)b * 512 + c4];
    double acc = (double)(long long)g_meanacc;
    float m = (float)(acc * (1.0 / 4294967296.0) / NELEM_GRID);
    __half2* A2 = reinterpret_cast<__half2*>(g_A);
    size_t base = (size_t)b * (KK / 2) + c4 * 2;
    A2[base + 0] = __floats2half2_rn(v.x, v.y);
    A2[base + 1] = __floats2half2_rn(v.z, v.w);
    float dx = v.x - m, dy = v.y - m, dz = v.z - m, dw = v.w - m;
    size_t base2 = base + (KIN / 2);
    A2[base2 + 0] = __floats2half2_rn(__expf(-dx * dx), __expf(-dy * dy));
    A2[base2 + 1] = __floats2half2_rn(__expf(-dz * dz), __expf(-dw * dw));
}

// ====== main GEMM: 128x128x32, A via smem (R5), B via direct frag LDG =====
__global__ __launch_bounds__(256, 2) void k_gemm(float* __restrict__ out) {
    extern __shared__ char smc[];
    uint32_t sb = (uint32_t)__cvta_generic_to_shared(smc);

    // reset mean accumulator for the next graph replay
    if (blockIdx.x == 0 && blockIdx.y == 0 && threadIdx.x == 0) g_meanacc = 0ULL;

    int tid  = threadIdx.x;
    int warp = tid >> 5, lane = tid & 31;
    int wm = warp & 3;         // 4 warps along M -> 32 rows each
    int wn = warp >> 2;        // 2 warps along N -> 64 cols each
    int g  = lane >> 2;        // 0..7
    int tg = lane & 3;         // 0..3
    int m0 = blockIdx.y * BM;
    int n0 = blockIdx.x * BN;

    // A ldmatrix per-lane offsets (bytes, within one stage) -- R5 mapping
    uint32_t a_lane = (uint32_t)((lane & 15) * (ASTR * 2) + (lane >> 4) * 16);
    uint32_t a_warp = (uint32_t)(wm * 32 * (ASTR * 2));

    // A cp.async mapping: 512 16B-chunks per stage, 2/thread
    int r0 = tid >> 1;
    int c0 = (tid & 1) * 2;
    const __half* Ag = g_A + (size_t)(m0 + r0) * KK + c0 * 8;
    uint32_t dA = (uint32_t)(r0 * (ASTR * 2) + c0 * 16);

    // B fragment base: this warp covers J = (n0/8) + wn*8 + f, f in 0..7
    const uint2* Bp = g_Bf + ((size_t)((n0 >> 3) + wn * 8)) * 32 + lane;

    float acc[2][8][4];
    #pragma unroll
    for (int i = 0; i < 2; i++)
        #pragma unroll
        for (int j = 0; j < 8; j++)
            #pragma unroll
            for (int k = 0; k < 4; k++) acc[i][j][k] = 0.f;

    // A prologue: stages 0..2
    #pragma unroll
    for (int s = 0; s < NSTAGE - 1; ++s) {
        int k0 = s * KTILE;
        cp16(sb + AOFF(s) + dA,      Ag + k0);
        cp16(sb + AOFF(s) + dA + 16, Ag + k0 + 8);
        asm volatile("cp.async.commit_group;");
    }

    // B prologue: slice 0 -> breg[0]
    uint2 breg[2][8];
    #pragma unroll
    for (int f = 0; f < 8; ++f)
        breg[0][f] = __ldg(Bp + f * 32);

    #pragma unroll 1
    for (int kt = 0; kt < NT; ++kt) {
        asm volatile("cp.async.wait_group %0;" :: "n"(NSTAGE - 2));
        __syncthreads();

        if (kt + NSTAGE - 1 < NT) {
            int s  = (kt + NSTAGE - 1) & (NSTAGE - 1);
            int k0 = (kt + NSTAGE - 1) * KTILE;
            cp16(sb + AOFF(s) + dA,      Ag + k0);
            cp16(sb + AOFF(s) + dA + 16, Ag + k0 + 8);
        }
        asm volatile("cp.async.commit_group;");

        int buf = kt & (NSTAGE - 1);
        uint32_t abase = sb + AOFF(buf) + a_warp + a_lane;

        #pragma unroll
        for (int s = 0; s < 2; ++s) {                 // two k16 slices; parity == s
            int Snext = kt * 2 + s + 1;               // next global slice (padded tail)
            // issue next slice's B fragment loads (consumed next iteration)
            #pragma unroll
            for (int f = 0; f < 8; ++f)
                breg[s ^ 1][f] = __ldg(Bp + (size_t)Snext * (NJ * 32) + f * 32);

            uint32_t af[2][4];
            ldsm4(af[0], abase + s * 32);
            ldsm4(af[1], abase + s * 32 + 16 * (ASTR * 2));

            #pragma unroll
            for (int f = 0; f < 8; ++f) {
                uint2 bb = breg[s][f];
                #pragma unroll
                for (int mf = 0; mf < 2; ++mf)
                    mma_f16(acc[mf][f], af[mf], bb.x, bb.y);
            }
        }
        __syncthreads();
    }

    // epilogue
    #pragma unroll
    for (int mf = 0; mf < 2; ++mf) {
        #pragma unroll
        for (int nf = 0; nf < 8; ++nf) {
            int row0 = m0 + wm * 32 + mf * 16 + g;
            int col  = n0 + wn * 64 + nf * 8 + tg * 2;
            float2 v0 = make_float2(acc[mf][nf][0], acc[mf][nf][1]);
            float2 v1 = make_float2(acc[mf][nf][2], acc[mf][nf][3]);
            *reinterpret_cast<float2*>(&out[(size_t)row0 * NN + col])       = v0;
            *reinterpret_cast<float2*>(&out[(size_t)(row0 + 8) * NN + col]) = v1;
        }
    }
}

// ============================= launch =====================================
extern "C" void kernel_launch(void* const* d_in, const int* in_sizes, int n_in,
                              void* d_out, int out_size) {
    const float* x    = (const float*)d_in[0];   // (8192, 2048)
    const float* bw   = (const float*)d_in[1];   // (2048, 2048)
    const float* grid = (const float*)d_in[2];   // (2048, 2048, 8)
    float* out = (float*)d_out;                  // (8192, 2048)

    cudaFuncSetAttribute(k_gemm, cudaFuncAttributeMaxDynamicSharedMemorySize, SMEM_TOTAL);

    k_gridsum<<<dim3(KIN / 32, NN / 32), 256>>>(grid);
    k_packWb<<<(128 * 256 * 32) / 256, 256>>>(bw);
    k_buildA<<<(MM * KIN / 4) / 256, 256>>>(x);
    k_gemm<<<dim3(NN / BN, MM / BM), 256, SMEM_TOTAL>>>(out);
}